// round 1
// baseline (speedup 1.0000x reference)
#include <cuda_runtime.h>

// Problem constants
#define B_    64
#define CIN_  64
#define L_    4096
#define COUT_ 128
#define K_    7
#define PAD_  3
#define LOUT_ (L_ / 2)

// Tiling
#define LT    64                 // L positions per block
#define LP    (LT + 2 * PAD_)    // 70 sign-tile width
#define LPS   72                 // padded smem stride
#define NTHR  256
#define LPT   32                 // L positions per thread (tile split in 2 halves)
#define CCH   8                  // cin chunk staged in smem

// One fused kernel: BN+sign tile in smem -> direct conv (register accumulators)
// -> alpha * PReLU -> maxpool(2,2) -> float4 stores.
// Block: (b, l-tile). 256 threads = 128 couts x 2 L-halves.
__global__ __launch_bounds__(NTHR, 2)
void bn_bin_conv_pool_kernel(const float* __restrict__ I,
                             const float* __restrict__ bn_gamma,
                             const float* __restrict__ bn_beta,
                             const float* __restrict__ bn_mean,
                             const float* __restrict__ bn_var,
                             const float* __restrict__ conv_w,
                             const float* __restrict__ alpha,
                             const float* __restrict__ prelu_w,
                             float* __restrict__ out)
{
    __shared__ float s_s[CIN_][LPS];        // sign tile: 64 x 72 = 18.4 KB
    __shared__ float s_w[COUT_][CCH][K_];   // weight chunk: 128 x 8 x 7 = 28.7 KB
    __shared__ float s_a[CIN_], s_b[CIN_];  // folded BN coefficients

    const int tid = threadIdx.x;
    const int b   = blockIdx.y;
    const int l0  = blockIdx.x * LT;

    // Fold BN: v = a * x + c
    if (tid < CIN_) {
        float a = bn_gamma[tid] / sqrtf(bn_var[tid] + 1e-5f);
        s_a[tid] = a;
        s_b[tid] = bn_beta[tid] - bn_mean[tid] * a;
    }
    __syncthreads();

    // Build sign tile. Out-of-range l -> 0 (this IS the conv zero padding:
    // conv input is sign(BN(x)), padded with zeros).
    for (int idx = tid; idx < CIN_ * LP; idx += NTHR) {
        int cin = idx / LP;
        int j   = idx - cin * LP;
        int l   = l0 - PAD_ + j;
        float s = 0.f;
        if (l >= 0 && l < L_) {
            float v = fmaf(s_a[cin], I[(b * CIN_ + cin) * L_ + l], s_b[cin]);
            s = (v > 0.f) ? 1.f : ((v < 0.f) ? -1.f : 0.f);
        }
        s_s[cin][j] = s;
    }

    const int cout  = tid & (COUT_ - 1);
    const int half  = tid >> 7;
    const int lbase = half * LPT;

    float acc[LPT];
    #pragma unroll
    for (int i = 0; i < LPT; i++) acc[i] = 0.f;

    for (int c0 = 0; c0 < CIN_; c0 += CCH) {
        __syncthreads();  // covers sign tile (first iter) and s_w reuse (later iters)
        // Stage weight chunk: conv_w[cout][c0 .. c0+7][0..6] is a contiguous
        // 56-float run per cout -> coalesced-ish loads.
        for (int idx = tid; idx < COUT_ * CCH * K_; idx += NTHR) {
            int co = idx / (CCH * K_);
            int r  = idx - co * (CCH * K_);
            (&s_w[co][0][0])[r] = conv_w[co * (CIN_ * K_) + c0 * K_ + r];
        }
        __syncthreads();

        #pragma unroll
        for (int cc = 0; cc < CCH; cc++) {
            // Broadcast loads (all lanes in a warp read the same address).
            float sv[LPT + K_ - 1];
            #pragma unroll
            for (int j = 0; j < LPT + K_ - 1; j++)
                sv[j] = s_s[c0 + cc][lbase + j];
            #pragma unroll
            for (int k = 0; k < K_; k++) {
                float w = s_w[cout][cc][k];
                #pragma unroll
                for (int i = 0; i < LPT; i++)
                    acc[i] = fmaf(w, sv[i + k], acc[i]);
            }
        }
    }

    // Epilogue: alpha scale, PReLU, maxpool(2,2). Pool pairs are adjacent
    // accumulators in this thread. 16 pooled outputs -> 4x float4 stores.
    const float al = alpha[cout];
    const float pw = prelu_w[0];
    float4* o4 = reinterpret_cast<float4*>(
        out + (b * COUT_ + cout) * LOUT_ + (l0 + lbase) / 2);

    #pragma unroll
    for (int v = 0; v < LPT / 8; v++) {
        float p[4];
        #pragma unroll
        for (int q = 0; q < 4; q++) {
            float y0 = acc[v * 8 + 2 * q]     * al;
            float y1 = acc[v * 8 + 2 * q + 1] * al;
            y0 = (y0 > 0.f) ? y0 : pw * y0;
            y1 = (y1 > 0.f) ? y1 : pw * y1;
            p[q] = fmaxf(y0, y1);
        }
        o4[v] = make_float4(p[0], p[1], p[2], p[3]);
    }
}

extern "C" void kernel_launch(void* const* d_in, const int* in_sizes, int n_in,
                              void* d_out, int out_size)
{
    const float* I        = (const float*)d_in[0];
    const float* bn_gamma = (const float*)d_in[1];
    const float* bn_beta  = (const float*)d_in[2];
    const float* bn_mean  = (const float*)d_in[3];
    const float* bn_var   = (const float*)d_in[4];
    const float* conv_w   = (const float*)d_in[5];
    const float* alpha    = (const float*)d_in[6];
    const float* prelu_w  = (const float*)d_in[7];
    float* out = (float*)d_out;

    dim3 grid(L_ / LT, B_);
    bn_bin_conv_pool_kernel<<<grid, NTHR>>>(
        I, bn_gamma, bn_beta, bn_mean, bn_var, conv_w, alpha, prelu_w, out);
}

// round 4
// speedup vs baseline: 3.8268x; 3.8268x over previous
#include <cuda_runtime.h>
#include <cuda_fp16.h>
#include <cstdint>

// ---------------- problem constants ----------------
#define B_     64
#define CIN_   64
#define L_     4096
#define COUT_  128
#define K_     7
#define LOUT_  2048

// ---------------- tiling ----------------
#define TILE_L  128                 // l positions per CTA tile
#define NTILES  2048                // B_ * (L_/TILE_L)
#define ROWS    134                 // TILE_L + 6 halo
#define NTHR    256
#define GRID    148

// ---------------- smem layout ----------------
// A: weights, 7 taps x [128 cout x 64 cin] fp16, row stride 72 halfs (144B)
//    -> ldmatrix rows differ by 36 words = 4 banks: conflict-free.
// B: sign tile, 134 rows (l) x 64 cin fp16, same 72-half stride
//    -> lds.b32 bank = (4*row + q) % 32: conflict-free.
#define SA_STRIDE 72
#define SB_STRIDE 72
#define SM_A      0
#define SM_A_SZ   (7 * 128 * SA_STRIDE * 2)   // 129024
#define SM_B      SM_A_SZ
#define SM_B_SZ   (ROWS * SB_STRIDE * 2)      // 19296
#define SM_BN     (SM_B + SM_B_SZ)            // 148320
#define SM_TOTAL  (SM_BN + 512)               // 148832

// ---------------- PTX helpers ----------------
__device__ __forceinline__ uint32_t smem_u32(const void* p) {
    uint32_t a;
    asm("{ .reg .u64 t; cvta.to.shared.u64 t, %1; cvt.u32.u64 %0, t; }"
        : "=r"(a) : "l"(p));
    return a;
}
__device__ __forceinline__ uint32_t lds32(uint32_t a) {
    uint32_t v;
    asm volatile("ld.shared.b32 %0, [%1];" : "=r"(v) : "r"(a));
    return v;
}
__device__ __forceinline__ void ldsm4(uint32_t* r, uint32_t a) {
    asm volatile("ldmatrix.sync.aligned.m8n8.x4.shared.b16 {%0,%1,%2,%3}, [%4];"
        : "=r"(r[0]), "=r"(r[1]), "=r"(r[2]), "=r"(r[3]) : "r"(a));
}
__device__ __forceinline__ void mma16816(float* d,
                                         uint32_t a0, uint32_t a1, uint32_t a2, uint32_t a3,
                                         uint32_t b0, uint32_t b1) {
    asm volatile("mma.sync.aligned.m16n8k16.row.col.f32.f16.f16.f32 "
                 "{%0,%1,%2,%3}, {%4,%5,%6,%7}, {%8,%9}, {%0,%1,%2,%3};"
                 : "+f"(d[0]), "+f"(d[1]), "+f"(d[2]), "+f"(d[3])
                 : "r"(a0), "r"(a1), "r"(a2), "r"(a3), "r"(b0), "r"(b1));
}

// ---------------- kernel ----------------
// Persistent: weights -> smem fp16 once, then loop over (b, l-tile) tiles.
// Warp w: cout half wh = w/4 (64 couts), l quarter wq = w%4 (32 l).
// Warp tile = 64 cout x 32 l = 4 m-frags x 4 n-frags of m16n8k16.
// 7 conv taps = row-shifted reads of the shared sign tile (GEMM K = cin = 64).
__global__ __launch_bounds__(NTHR, 1)
void bn_bin_conv_pool_hmma(const float* __restrict__ I,
                           const float* __restrict__ bn_gamma,
                           const float* __restrict__ bn_beta,
                           const float* __restrict__ bn_mean,
                           const float* __restrict__ bn_var,
                           const float* __restrict__ conv_w,
                           const float* __restrict__ alpha,
                           const float* __restrict__ prelu_w,
                           float* __restrict__ out)
{
    extern __shared__ __align__(16) char smem[];
    const uint32_t sm0 = smem_u32(smem);
    __half* sA  = (__half*)smem;
    __half* sB  = (__half*)(smem + SM_B);
    float*  sa  = (float*)(smem + SM_BN);
    float*  sbn = sa + CIN_;

    const int tid  = threadIdx.x;
    const int lane = tid & 31;
    const int wid  = tid >> 5;
    const int wh   = wid >> 2;      // cout half
    const int wq   = wid & 3;       // l quarter
    const int r    = lane >> 2;     // fragment row (0..7)
    const int q    = lane & 3;      // fragment col group (0..3)

    // BN fold: v = sa*x + sbn
    if (tid < CIN_) {
        float a = bn_gamma[tid] * rsqrtf(bn_var[tid] + 1e-5f);
        sa[tid]  = a;
        sbn[tid] = bn_beta[tid] - bn_mean[tid] * a;
    }

    // Weights -> fp16 smem, [tap][cout][cin], once per CTA (coalesced reads)
    for (int idx = tid; idx < COUT_ * CIN_ * K_; idx += NTHR) {
        int k    = idx % K_;
        int rest = idx / K_;
        int cin  = rest & (CIN_ - 1);
        int cout = rest >> 6;
        sA[(k * COUT_ + cout) * SA_STRIDE + cin] = __float2half(conv_w[idx]);
    }

    // ldmatrix.x4 per-thread address components:
    // tile j = lane/8 -> (j&1): m 0/8 offset, (j>>1): k 0/8 offset; i = row in tile
    const int jj = lane >> 3, ii = lane & 7;
    const int a_row  = (jj & 1) * 8 + ii;
    const int a_colh = (jj >> 1) * 8;     // halfs

    float al[4][2];
    #pragma unroll
    for (int mf = 0; mf < 4; mf++) {
        al[mf][0] = alpha[wh * 64 + mf * 16 + r];
        al[mf][1] = alpha[wh * 64 + mf * 16 + r + 8];
    }
    const float pw = prelu_w[0];
    __syncthreads();

    const uint32_t sAu = sm0;
    const uint32_t sBu = sm0 + SM_B;

    for (int t = blockIdx.x; t < NTILES; t += GRID) {
        const int bb = t >> 5;            // 32 l-tiles per batch
        const int l0 = (t & 31) << 7;     // * TILE_L

        // ---- build sign tile: rows l0-3 .. l0+130, [row][cin] fp16 ----
        const float* Ib = I + (size_t)bb * CIN_ * L_;
        #pragma unroll 4
        for (int idx = tid; idx < CIN_ * ROWS; idx += NTHR) {
            int cin = idx / ROWS;
            int row = idx - cin * ROWS;
            int l   = l0 - 3 + row;
            float s = 0.f;
            if ((unsigned)l < (unsigned)L_) {
                float v = fmaf(sa[cin], Ib[cin * L_ + l], sbn[cin]);
                s = (v > 0.f) ? 1.f : ((v < 0.f) ? -1.f : 0.f);
            }
            sB[row * SB_STRIDE + cin] = __float2half(s);
        }
        __syncthreads();

        // ---- MMA mainloop: 7 taps x 4 cin-chunks ----
        float acc[4][4][4];
        #pragma unroll
        for (int mf = 0; mf < 4; mf++)
            #pragma unroll
            for (int nf = 0; nf < 4; nf++)
                #pragma unroll
                for (int e = 0; e < 4; e++) acc[mf][nf][e] = 0.f;

        for (int k = 0; k < K_; k++) {          // not unrolled: keep I$ small
            #pragma unroll
            for (int c = 0; c < 4; c++) {
                uint32_t af[4][4];
                #pragma unroll
                for (int mf = 0; mf < 4; mf++) {
                    uint32_t ad = sAu + (uint32_t)(
                        ((k * COUT_ + wh * 64 + mf * 16 + a_row) * SA_STRIDE
                         + c * 16 + a_colh) * 2);
                    ldsm4(af[mf], ad);
                }
                #pragma unroll
                for (int nf = 0; nf < 4; nf++) {
                    // tap k shifts the l row: smem row = local_l + k (rows start at l0-3)
                    uint32_t brow = (uint32_t)(wq * 32 + nf * 8 + r + k);
                    uint32_t bad  = sBu + brow * (SB_STRIDE * 2) + c * 32 + q * 4;
                    uint32_t b0 = lds32(bad);
                    uint32_t b1 = lds32(bad + 16);
                    #pragma unroll
                    for (int mf = 0; mf < 4; mf++)
                        mma16816(acc[mf][nf],
                                 af[mf][0], af[mf][1], af[mf][2], af[mf][3],
                                 b0, b1);
                }
            }
        }

        // ---- epilogue: alpha, PReLU, maxpool(2,2) ----
        // D frag: c0:(m=r, n=2q) c1:(r,2q+1) c2:(r+8,2q) c3:(r+8,2q+1)
        // pool pairs = (c0,c1) and (c2,c3): adjacent l positions.
        float* ob = out + ((size_t)bb * COUT_) * LOUT_ + (l0 >> 1);
        #pragma unroll
        for (int mf = 0; mf < 4; mf++) {
            const int c0 = wh * 64 + mf * 16 + r;
            #pragma unroll
            for (int nf = 0; nf < 4; nf++) {
                const int lp = wq * 16 + nf * 4 + q;
                float y0 = acc[mf][nf][0] * al[mf][0];
                float y1 = acc[mf][nf][1] * al[mf][0];
                y0 = (y0 > 0.f) ? y0 : pw * y0;
                y1 = (y1 > 0.f) ? y1 : pw * y1;
                ob[(size_t)c0 * LOUT_ + lp] = fmaxf(y0, y1);
                float y2 = acc[mf][nf][2] * al[mf][1];
                float y3 = acc[mf][nf][3] * al[mf][1];
                y2 = (y2 > 0.f) ? y2 : pw * y2;
                y3 = (y3 > 0.f) ? y3 : pw * y3;
                ob[(size_t)(c0 + 8) * LOUT_ + lp] = fmaxf(y2, y3);
            }
        }
        __syncthreads();   // all warps done with sB before next tile overwrites
    }
}

// ---------------- launch ----------------
extern "C" void kernel_launch(void* const* d_in, const int* in_sizes, int n_in,
                              void* d_out, int out_size)
{
    const float* I        = (const float*)d_in[0];
    const float* bn_gamma = (const float*)d_in[1];
    const float* bn_beta  = (const float*)d_in[2];
    const float* bn_mean  = (const float*)d_in[3];
    const float* bn_var   = (const float*)d_in[4];
    const float* conv_w   = (const float*)d_in[5];
    const float* alpha    = (const float*)d_in[6];
    const float* prelu_w  = (const float*)d_in[7];
    float* out = (float*)d_out;

    cudaFuncSetAttribute(bn_bin_conv_pool_hmma,
                         cudaFuncAttributeMaxDynamicSharedMemorySize, SM_TOTAL);
    bn_bin_conv_pool_hmma<<<GRID, NTHR, SM_TOTAL>>>(
        I, bn_gamma, bn_beta, bn_mean, bn_var, conv_w, alpha, prelu_w, out);
}

// round 5
// speedup vs baseline: 4.9114x; 1.2834x over previous
#include <cuda_runtime.h>
#include <cuda_fp16.h>
#include <cstdint>

// ---------------- problem constants ----------------
#define B_     64
#define CIN_   64
#define L_     4096
#define COUT_  128
#define K_     7
#define LOUT_  2048

// ---------------- tiling ----------------
#define TILE_L  192                 // l positions per CTA tile
#define LT_PB   22                  // ceil(4096/192): last tile ragged (64 l)
#define NTILES  (B_ * LT_PB)        // 1408
#define ROWS    198                 // TILE_L + 6 halo
#define NTHR    384                 // 12 warps: wh(2 cout halves) x wq(6 l sixths)
#define GRID    148

// ---------------- smem layout ----------------
// A: weights 7 x [128 cout x 64 cin] fp16, stride 64 halfs (128B) + SW128 XOR
//    swizzle -> ldmatrix conflict-free, 114688 B.
// B: sign tile x2 (ping-pong), [198 row x 64 cin] fp16, stride 72 halfs ->
//    lds.b32 bank = (4*row + q) % 32 conflict-free. 2 x 28512 B.
// RAW: cp.async staging of fp32 input for the NEXT tile, [64 cin x 200 l].
#define SB_STRIDE 72
#define SM_A      0
#define SM_A_SZ   (K_ * COUT_ * CIN_ * 2)     // 114688
#define SM_B      SM_A_SZ
#define SB_BUF    (ROWS * SB_STRIDE * 2)      // 28512
#define SM_RAW    (SM_B + 2 * SB_BUF)         // 171712 (16B aligned)
#define RAW_STRIDE 200                        // floats per cin (l0-4 .. l0+195)
#define NCHUNK    50                          // 16B chunks per cin
#define NOPS      (CIN_ * NCHUNK)             // 3200 cp.async ops per tile
#define SM_RAW_SZ (CIN_ * RAW_STRIDE * 4)     // 51200
#define SM_BN     (SM_RAW + SM_RAW_SZ)        // 222912
#define SM_TOTAL  (SM_BN + 512)               // 223424

// ---------------- PTX helpers ----------------
__device__ __forceinline__ uint32_t smem_u32(const void* p) {
    uint32_t a;
    asm("{ .reg .u64 t; cvta.to.shared.u64 t, %1; cvt.u32.u64 %0, t; }"
        : "=r"(a) : "l"(p));
    return a;
}
__device__ __forceinline__ uint32_t lds32(uint32_t a) {
    uint32_t v;
    asm volatile("ld.shared.b32 %0, [%1];" : "=r"(v) : "r"(a));
    return v;
}
__device__ __forceinline__ void ldsm4(uint32_t* r, uint32_t a) {
    asm volatile("ldmatrix.sync.aligned.m8n8.x4.shared.b16 {%0,%1,%2,%3}, [%4];"
        : "=r"(r[0]), "=r"(r[1]), "=r"(r[2]), "=r"(r[3]) : "r"(a));
}
__device__ __forceinline__ void mma16816(float* d,
                                         uint32_t a0, uint32_t a1, uint32_t a2, uint32_t a3,
                                         uint32_t b0, uint32_t b1) {
    asm volatile("mma.sync.aligned.m16n8k16.row.col.f32.f16.f16.f32 "
                 "{%0,%1,%2,%3}, {%4,%5,%6,%7}, {%8,%9}, {%0,%1,%2,%3};"
                 : "+f"(d[0]), "+f"(d[1]), "+f"(d[2]), "+f"(d[3])
                 : "r"(a0), "r"(a1), "r"(a2), "r"(a3), "r"(b0), "r"(b1));
}
__device__ __forceinline__ void cp16(uint32_t dst, const void* src, int sz) {
    asm volatile("cp.async.cg.shared.global [%0], [%1], 16, %2;"
                 :: "r"(dst), "l"(src), "r"(sz) : "memory");
}
#define CP_COMMIT() asm volatile("cp.async.commit_group;" ::: "memory")
#define CP_WAIT0()  asm volatile("cp.async.wait_group 0;" ::: "memory")

// SW128-style XOR swizzle on byte offsets within the A region (128B rows)
__device__ __forceinline__ uint32_t swA(uint32_t o) { return o ^ ((o >> 3) & 0x70); }

// ---------------- kernel ----------------
// Persistent CTAs. Weights staged once. Per tile: cp.async prefetch of next
// tile's raw fp32 overlaps this tile's MMA; sign conversion (own-thread data
// only) lands in the ping-pong sign buffer; one __syncthreads per tile.
__global__ __launch_bounds__(NTHR, 1)
void bn_bin_conv_pool_hmma2(const float* __restrict__ I,
                            const float* __restrict__ bn_gamma,
                            const float* __restrict__ bn_beta,
                            const float* __restrict__ bn_mean,
                            const float* __restrict__ bn_var,
                            const float* __restrict__ conv_w,
                            const float* __restrict__ alpha,
                            const float* __restrict__ prelu_w,
                            float* __restrict__ out)
{
    extern __shared__ __align__(16) char smem[];
    const uint32_t sm0 = smem_u32(smem);
    float* sa  = (float*)(smem + SM_BN);
    float* sbn = sa + CIN_;

    const int tid  = threadIdx.x;
    const int lane = tid & 31;
    const int wid  = tid >> 5;
    const int wh   = wid / 6;       // cout half (0..1)
    const int wq   = wid % 6;       // l sixth  (0..5)
    const int r    = lane >> 2;     // frag row
    const int q    = lane & 3;      // frag col group

    // BN fold: v = sa*x + sbn
    if (tid < CIN_) {
        float a = bn_gamma[tid] * rsqrtf(bn_var[tid] + 1e-5f);
        sa[tid]  = a;
        sbn[tid] = bn_beta[tid] - bn_mean[tid] * a;
    }

    // Weights -> fp16, [tap][cout][cin] stride 64, SW128 swizzle, once per CTA
    for (int idx = tid; idx < COUT_ * CIN_ * K_; idx += NTHR) {
        int k    = idx % K_;
        int rest = idx / K_;
        int cin  = rest & (CIN_ - 1);
        int cout = rest >> 6;
        uint32_t off = (uint32_t)((((k * COUT_ + cout) * CIN_) + cin) * 2);
        *(__half*)(smem + SM_A + swA(off)) = __float2half(conv_w[idx]);
    }

    // ldmatrix per-thread address components
    const int jj = lane >> 3, ii = lane & 7;
    const int a_row  = (jj & 1) * 8 + ii;
    const int a_colh = (jj >> 1) * 8;

    float al[4][2];
    #pragma unroll
    for (int mf = 0; mf < 4; mf++) {
        al[mf][0] = alpha[wh * 64 + mf * 16 + r];
        al[mf][1] = alpha[wh * 64 + mf * 16 + r + 8];
    }
    const float pw = prelu_w[0];

    // ---- prefetch issue: raw fp32 for tile t into SM_RAW ----
    auto issue_raw = [&](int t) {
        int bb = t / LT_PB;
        int l0 = (t - bb * LT_PB) * TILE_L;
        const float* Ib = I + (size_t)bb * CIN_ * L_;
        #pragma unroll 4
        for (int o = tid; o < NOPS; o += NTHR) {
            int cin = o / NCHUNK, ch = o - cin * NCHUNK;
            int gl = l0 - 4 + ch * 4;                       // 16B aligned
            int sz = ((unsigned)gl < (unsigned)L_) ? 16 : 0; // gl in [0, L-4]
            int glc = sz ? gl : 0;
            cp16(sm0 + SM_RAW + (uint32_t)((cin * RAW_STRIDE + ch * 4) * 4),
                 Ib + (size_t)cin * L_ + glc, sz);
        }
        CP_COMMIT();
    };

    // ---- convert own-thread raw data -> sign tile at smem byte offset sbOff ----
    auto convert_raw = [&](int t, uint32_t sbOff) {
        CP_WAIT0();
        int bb = t / LT_PB;
        int l0 = (t - bb * LT_PB) * TILE_L;
        #pragma unroll 4
        for (int o = tid; o < NOPS; o += NTHR) {
            int cin = o / NCHUNK, ch = o - cin * NCHUNK;
            const float4 v = *(const float4*)(smem + SM_RAW
                                + (size_t)((cin * RAW_STRIDE + ch * 4) * 4));
            float aa = sa[cin], bv = sbn[cin];
            float vv[4] = {v.x, v.y, v.z, v.w};
            #pragma unroll
            for (int j = 0; j < 4; j++) {
                int rr = ch * 4 + j - 1;           // sign-tile row
                if ((unsigned)rr < (unsigned)ROWS) {
                    int l = l0 - 3 + rr;
                    float s = 0.f;
                    if ((unsigned)l < (unsigned)L_) {
                        float x = fmaf(aa, vv[j], bv);
                        s = (x > 0.f) ? 1.f : ((x < 0.f) ? -1.f : 0.f);
                    }
                    *(__half*)(smem + sbOff + (uint32_t)((rr * SB_STRIDE + cin) * 2))
                        = __float2half(s);
                }
            }
        }
    };

    // ---- prologue: fill sign buffer 0 for the first tile ----
    issue_raw(blockIdx.x);
    __syncthreads();                 // BN + weights visible
    convert_raw(blockIdx.x, SM_B);
    __syncthreads();

    int cur = 0;
    for (int t = blockIdx.x; t < NTILES; t += GRID) {
        const int bb = t / LT_PB;
        const int l0 = (t - bb * LT_PB) * TILE_L;
        const int tn = t + GRID;

        if (tn < NTILES) issue_raw(tn);   // overlaps with MMA below

        const uint32_t sBu = sm0 + SM_B + (uint32_t)(cur * SB_BUF);

        // ---- MMA mainloop: 7 taps x 4 cin-chunks, warp = 64 cout x 32 l ----
        float acc[4][4][4];
        #pragma unroll
        for (int mf = 0; mf < 4; mf++)
            #pragma unroll
            for (int nf = 0; nf < 4; nf++)
                #pragma unroll
                for (int e = 0; e < 4; e++) acc[mf][nf][e] = 0.f;

        #pragma unroll
        for (int k = 0; k < K_; k++) {
            #pragma unroll
            for (int c = 0; c < 4; c++) {
                uint32_t af[4][4];
                #pragma unroll
                for (int mf = 0; mf < 4; mf++) {
                    uint32_t o = (uint32_t)((((k * COUT_ + wh * 64 + mf * 16 + a_row)
                                  * CIN_) + c * 16 + a_colh) * 2);
                    ldsm4(af[mf], sm0 + SM_A + swA(o));
                }
                #pragma unroll
                for (int nf = 0; nf < 4; nf++) {
                    uint32_t brow = (uint32_t)(wq * 32 + nf * 8 + r + k);
                    uint32_t bad  = sBu + brow * (SB_STRIDE * 2) + c * 32 + q * 4;
                    uint32_t b0 = lds32(bad);
                    uint32_t b1 = lds32(bad + 16);
                    #pragma unroll
                    for (int mf = 0; mf < 4; mf++)
                        mma16816(acc[mf][nf],
                                 af[mf][0], af[mf][1], af[mf][2], af[mf][3],
                                 b0, b1);
                }
            }
        }

        // ---- epilogue: alpha, PReLU, maxpool(2,2), ragged-tile guard ----
        const int lim = (L_ - l0) >> 1;   // pooled cols valid in this tile
        float* ob = out + ((size_t)bb * COUT_) * LOUT_ + (l0 >> 1);
        #pragma unroll
        for (int mf = 0; mf < 4; mf++) {
            const int c0 = wh * 64 + mf * 16 + r;
            #pragma unroll
            for (int nf = 0; nf < 4; nf++) {
                const int lp = wq * 16 + nf * 4 + q;
                if (lp < lim) {
                    float y0 = acc[mf][nf][0] * al[mf][0];
                    float y1 = acc[mf][nf][1] * al[mf][0];
                    y0 = (y0 > 0.f) ? y0 : pw * y0;
                    y1 = (y1 > 0.f) ? y1 : pw * y1;
                    ob[(size_t)c0 * LOUT_ + lp] = fmaxf(y0, y1);
                    float y2 = acc[mf][nf][2] * al[mf][1];
                    float y3 = acc[mf][nf][3] * al[mf][1];
                    y2 = (y2 > 0.f) ? y2 : pw * y2;
                    y3 = (y3 > 0.f) ? y3 : pw * y3;
                    ob[(size_t)(c0 + 8) * LOUT_ + lp] = fmaxf(y2, y3);
                }
            }
        }

        if (tn < NTILES) convert_raw(tn, SM_B + (uint32_t)((cur ^ 1) * SB_BUF));
        __syncthreads();   // sign buffer handoff + raw reuse + sB read-complete
        cur ^= 1;
    }
}

// ---------------- launch ----------------
extern "C" void kernel_launch(void* const* d_in, const int* in_sizes, int n_in,
                              void* d_out, int out_size)
{
    const float* I        = (const float*)d_in[0];
    const float* bn_gamma = (const float*)d_in[1];
    const float* bn_beta  = (const float*)d_in[2];
    const float* bn_mean  = (const float*)d_in[3];
    const float* bn_var   = (const float*)d_in[4];
    const float* conv_w   = (const float*)d_in[5];
    const float* alpha    = (const float*)d_in[6];
    const float* prelu_w  = (const float*)d_in[7];
    float* out = (float*)d_out;

    cudaFuncSetAttribute(bn_bin_conv_pool_hmma2,
                         cudaFuncAttributeMaxDynamicSharedMemorySize, SM_TOTAL);
    bn_bin_conv_pool_hmma2<<<GRID, NTHR, SM_TOTAL>>>(
        I, bn_gamma, bn_beta, bn_mean, bn_var, conv_w, alpha, prelu_w, out);
}